// round 16
// baseline (speedup 1.0000x reference)
#include <cuda_runtime.h>
#include <cstdint>

typedef unsigned long long u64;
typedef unsigned int u32;
typedef unsigned short u16;

#define BH 64

// Fragment images (m16n8k16 per-lane order)
__device__ uint4 g_XF[8*8*128*32];       // x  B-frags bf16 split {b0h,b1h,b0l,b1l}
__device__ uint4 g_WF[64*3*8*32*2];      // Wqkv A-frags bf16 {hi,lo}
__device__ uint4 g_WoF[8*8*8*32*2];      // Wo A-frags bf16 {hi,lo}
__device__ uint4 g_HF[8*8*128*32];       // H  B-frags bf16 (written by attn)
__device__ uint4 g_KF[BH*64*32*2];       // attn A-frags (K bf16, *SCL) {hi,lo}
__device__ uint4 g_QF[BH*128*32];        // attn B-frags (Q bf16) {b0h,b1h,b0l,b1l}
__device__ uint4 g_VF[BH*64*32*2];       // attn B-frags (V FP16) {hi,lo}

// ---------------- helpers ----------------
__device__ __forceinline__ float ex2(float x) {
    float y; asm("ex2.approx.ftz.f32 %0, %1;" : "=f"(y) : "f"(x)); return y;
}
__device__ __forceinline__ u32 cvt2bf(float hi, float lo){
    u32 r; asm("cvt.rn.bf16x2.f32 %0, %1, %2;" : "=r"(r) : "f"(hi), "f"(lo)); return r;
}
// saturating fp16 pack: overflow clamps to max finite (no Inf/NaN possible)
__device__ __forceinline__ u32 cvt2h(float hi, float lo){
    u32 r; asm("cvt.rn.satfinite.f16x2.f32 %0, %1, %2;" : "=r"(r) : "f"(hi), "f"(lo)); return r;
}
__device__ __forceinline__ float f16lo(u32 h){
    float f; asm("{ .reg .b16 l, u; mov.b32 {l, u}, %1; cvt.f32.f16 %0, l; }" : "=f"(f) : "r"(h)); return f;
}
__device__ __forceinline__ float f16hi(u32 h){
    float f; asm("{ .reg .b16 l, u; mov.b32 {l, u}, %1; cvt.f32.f16 %0, u; }" : "=f"(f) : "r"(h)); return f;
}
// bf16 split: (first, second) -> hi bf16x2 (second upper), lo bf16x2 residuals
__device__ __forceinline__ void split2(float a, float b, u32 &hi, u32 &lo) {
    hi = cvt2bf(b, a);
    float la = a - __uint_as_float(hi << 16);
    float lb = b - __uint_as_float(hi & 0xFFFF0000u);
    lo = cvt2bf(lb, la);
}
// fp16 split: (first, second) -> hi f16x2 (second upper), lo f16x2 residuals
__device__ __forceinline__ void split2h(float a, float b, u32 &hi, u32 &lo) {
    hi = cvt2h(b, a);
    lo = cvt2h(b - f16hi(hi), a - f16lo(hi));
}
__device__ __forceinline__ void mma_bf16(float d[4], const u32 a[4], u32 b0, u32 b1) {
    asm volatile("mma.sync.aligned.m16n8k16.row.col.f32.bf16.bf16.f32 "
        "{%0,%1,%2,%3}, {%4,%5,%6,%7}, {%8,%9}, {%0,%1,%2,%3};"
        : "+f"(d[0]),"+f"(d[1]),"+f"(d[2]),"+f"(d[3])
        : "r"(a[0]),"r"(a[1]),"r"(a[2]),"r"(a[3]), "r"(b0),"r"(b1));
}
__device__ __forceinline__ void mma_f16(float d[4], const u32 a[4], u32 b0, u32 b1) {
    asm volatile("mma.sync.aligned.m16n8k16.row.col.f32.f16.f16.f32 "
        "{%0,%1,%2,%3}, {%4,%5,%6,%7}, {%8,%9}, {%0,%1,%2,%3};"
        : "+f"(d[0]),"+f"(d[1]),"+f"(d[2]),"+f"(d[3])
        : "r"(a[0]),"r"(a[1]),"r"(a[2]),"r"(a[3]), "r"(b0),"r"(b1));
}
__device__ __forceinline__ void mma4(float d[4], const uint4 &a, u32 b0, u32 b1) {
    asm volatile("mma.sync.aligned.m16n8k16.row.col.f32.bf16.bf16.f32 "
        "{%0,%1,%2,%3}, {%4,%5,%6,%7}, {%8,%9}, {%0,%1,%2,%3};"
        : "+f"(d[0]),"+f"(d[1]),"+f"(d[2]),"+f"(d[3])
        : "r"(a.x),"r"(a.y),"r"(a.z),"r"(a.w), "r"(b0),"r"(b1));
}

// ---------------------------------------------------------------------------
// Kernel 1: prep_in — fragment images for x, Wqkv, Wo. grid 512 x 256.
// ---------------------------------------------------------------------------
__global__ __launch_bounds__(256) void prep_in(
    const float* __restrict__ x,
    const float* __restrict__ Wq, const float* __restrict__ Wk,
    const float* __restrict__ Wv, const float* __restrict__ Wo)
{
    int tid = blockIdx.x*256 + threadIdx.x;
    int stride = gridDim.x*256;

    // x B-fragments: 262144 entries
    for (int e = tid; e < 8*8*128*32; e += stride) {
        int lane = e & 31, nb = (e >> 5) & 127, kc = (e >> 12) & 7, b = e >> 15;
        int g = lane >> 2, t = lane & 3;
        const float* xb = x + b*128*1024 + nb*8 + g;
        int d = kc*16 + 2*t;
        float f0 = xb[(d    )*1024], f1 = xb[(d + 1)*1024];
        float f2 = xb[(d + 8)*1024], f3 = xb[(d + 9)*1024];
        uint4 o; u32 l0, l1;
        split2(f0, f1, o.x, l0);
        split2(f2, f3, o.y, l1);
        o.z = l0; o.w = l1;
        g_XF[e] = o;
    }
    // Wqkv A-fragments: 49152 entries
    for (int e = tid; e < 64*3*8*32; e += stride) {
        int lane = e & 31, kc = (e >> 5) & 7;
        int mb = (e >> 8) % 3, bh = (e >> 8) / 3;
        int g = lane >> 2, t = lane & 3;
        int b = bh >> 3, h = bh & 7;
        int m0 = mb*16 + g, m1 = m0 + 8, k0 = kc*16 + 2*t, k2 = k0 + 8;
        const float* Wm0 = (m0 < 16) ? Wq : ((m0 < 32) ? Wk : Wv);
        const float* Wm1 = (m1 < 16) ? Wq : ((m1 < 32) ? Wk : Wv);
        const float* r0p = Wm0 + ((h*8 + b)*16 + (m0 & 15))*128;
        const float* r1p = Wm1 + ((h*8 + b)*16 + (m1 & 15))*128;
        uint4 hi, lo;
        split2(r0p[k0], r0p[k0+1], hi.x, lo.x);
        split2(r1p[k0], r1p[k0+1], hi.y, lo.y);
        split2(r0p[k2], r0p[k2+1], hi.z, lo.z);
        split2(r1p[k2], r1p[k2+1], hi.w, lo.w);
        g_WF[e*2] = hi; g_WF[e*2 + 1] = lo;
    }
    // Wo A-fragments: 16384 entries
    for (int e = tid; e < 8*8*8*32; e += stride) {
        int lane = e & 31, kc = (e >> 5) & 7, mb = (e >> 8) & 7, b = e >> 11;
        int g = lane >> 2, t = lane & 3;
        int m0 = mb*16 + g, m1 = m0 + 8, k0 = kc*16 + 2*t, k2 = k0 + 8;
        const float* W = Wo + b*128*128;
        uint4 hi, lo;
        split2(W[m0*128 + k0], W[m0*128 + k0+1], hi.x, lo.x);
        split2(W[m1*128 + k0], W[m1*128 + k0+1], hi.y, lo.y);
        split2(W[m0*128 + k2], W[m0*128 + k2+1], hi.z, lo.z);
        split2(W[m1*128 + k2], W[m1*128 + k2+1], hi.w, lo.w);
        g_WoF[e*2] = hi; g_WoF[e*2 + 1] = lo;
    }
}

// ---------------------------------------------------------------------------
// Kernel 2: qkv_mma — QKV projection on tensor cores, fused with attn
// fragment construction. V fragments built as FP16 hi/lo.
// grid (64 bh, 8 l-tiles of 128), 256 thr.
// ---------------------------------------------------------------------------
__global__ __launch_bounds__(256) void qkv_mma()
{
    __shared__ float sQKV[48][128];

    int bh = blockIdx.x, b = bh >> 3;
    int lt = blockIdx.y;
    int tid = threadIdx.x, w = tid >> 5, lane = tid & 31;
    int g = lane >> 2, t = lane & 3;
    int nb0 = lt*16 + w*2;

    float acc[3][2][4] = {};
    #pragma unroll
    for (int kc = 0; kc < 8; kc++) {
        uint4 B0 = g_XF[((b*8 + kc)*128 + nb0    )*32 + lane];
        uint4 B1 = g_XF[((b*8 + kc)*128 + nb0 + 1)*32 + lane];
        #pragma unroll
        for (int mb = 0; mb < 3; mb++) {
            const uint4* af = g_WF + (((bh*3 + mb)*8 + kc)*32 + lane)*2;
            uint4 Ah = af[0], Al = af[1];
            mma4(acc[mb][0], Ah, B0.x, B0.y);
            mma4(acc[mb][0], Al, B0.x, B0.y);
            mma4(acc[mb][0], Ah, B0.z, B0.w);
            mma4(acc[mb][1], Ah, B1.x, B1.y);
            mma4(acc[mb][1], Al, B1.x, B1.y);
            mma4(acc[mb][1], Ah, B1.z, B1.w);
        }
    }
    // stage to smem (local cols)
    #pragma unroll
    for (int mb = 0; mb < 3; mb++) {
        #pragma unroll
        for (int nbi = 0; nbi < 2; nbi++) {
            int col = (w*2 + nbi)*8 + 2*t;
            int r0 = mb*16 + g;
            sQKV[r0    ][col    ] = acc[mb][nbi][0];
            sQKV[r0    ][col + 1] = acc[mb][nbi][1];
            sQKV[r0 + 8][col    ] = acc[mb][nbi][2];
            sQKV[r0 + 8][col + 1] = acc[mb][nbi][3];
        }
    }
    __syncthreads();

    // Phase 2: fragment construction (sourced from smem)
    const float SCLF = 0.25f * 1.4426950408889634f;  // scale * log2(e)
    {   // K A-fragments (scaled, bf16 split)
        int bb = tid >> 5, l2 = tid & 31, g2 = l2 >> 2, t2 = l2 & 3;
        int c0 = bb*16 + g2, c1 = c0 + 8;
        int k0 = 2*t2, k2 = 2*t2 + 8;
        float f0 = sQKV[16 + k0    ][c0] * SCLF;
        float f1 = sQKV[16 + k0 + 1][c0] * SCLF;
        float f2 = sQKV[16 + k0    ][c1] * SCLF;
        float f3 = sQKV[16 + k0 + 1][c1] * SCLF;
        float f4 = sQKV[16 + k2    ][c0] * SCLF;
        float f5 = sQKV[16 + k2 + 1][c0] * SCLF;
        float f6 = sQKV[16 + k2    ][c1] * SCLF;
        float f7 = sQKV[16 + k2 + 1][c1] * SCLF;
        uint4 hi, lo;
        split2(f0, f1, hi.x, lo.x);
        split2(f2, f3, hi.y, lo.y);
        split2(f4, f5, hi.z, lo.z);
        split2(f6, f7, hi.w, lo.w);
        int idx = ((bh*64 + lt*8 + bb)*32 + l2)*2;
        g_KF[idx] = hi; g_KF[idx + 1] = lo;
    }
    #pragma unroll
    for (int s2 = 0; s2 < 2; s2++) {  // Q B-fragments (bf16 split)
        int e = s2*256 + tid;
        int cc = e >> 5, l2 = e & 31, g2 = l2 >> 2, t2 = l2 & 3;
        int i = cc*8 + g2;
        float f0 = sQKV[2*t2    ][i];
        float f1 = sQKV[2*t2 + 1][i];
        float f2 = sQKV[2*t2 + 8][i];
        float f3 = sQKV[2*t2 + 9][i];
        uint4 o; u32 l0, l1;
        split2(f0, f1, o.x, l0);
        split2(f2, f3, o.y, l1);
        o.z = l0; o.w = l1;
        g_QF[(bh*128 + lt*16 + cc)*32 + l2] = o;
    }
    {   // V B-fragments (FP16 split hi/lo)
        int bb = tid >> 5, l2 = tid & 31, g2 = l2 >> 2, t2 = l2 & 3;
        int i0 = bb*16;
        float a0 = sQKV[32 + g2    ][i0 + 2*t2];
        float a1 = sQKV[32 + g2    ][i0 + 2*t2 + 1];
        float a2 = sQKV[32 + g2    ][i0 + 2*t2 + 8];
        float a3 = sQKV[32 + g2    ][i0 + 2*t2 + 9];
        float c0 = sQKV[32 + g2 + 8][i0 + 2*t2];
        float c1 = sQKV[32 + g2 + 8][i0 + 2*t2 + 1];
        float c2 = sQKV[32 + g2 + 8][i0 + 2*t2 + 8];
        float c3 = sQKV[32 + g2 + 8][i0 + 2*t2 + 9];
        uint4 hi, lo;
        split2h(a0, a1, hi.x, lo.x);
        split2h(a2, a3, hi.y, lo.y);
        split2h(c0, c1, hi.z, lo.z);
        split2h(c2, c3, hi.w, lo.w);
        int idx = ((bh*64 + lt*8 + bb)*32 + l2)*2;
        g_VF[idx] = hi; g_VF[idx + 1] = lo;
    }
}

// ---------------------------------------------------------------------------
// Kernel 3: attn — flash attention, 2-way chunk-interleaved; scores bf16
// 3-term; P in FP16 biased 2^-12 (satfinite), PV = ph*Vh + ph*Vl.
// grid (64 bh, 16 jtiles of 64), 128 thr.
// ---------------------------------------------------------------------------
#define BIAS 12.0f
__global__ __launch_bounds__(128) void attn_kernel()
{
    int bh = blockIdx.x, jt = blockIdx.y, tid = threadIdx.x;
    int w = tid >> 5, lane = tid & 31;

    const uint4* kf = g_KF + ((bh*64 + jt*4 + w)*32 + lane)*2;
    uint4 khv = kf[0], klv = kf[1];
    u32 kh[4] = {khv.x, khv.y, khv.z, khv.w};
    u32 kl[4] = {klv.x, klv.y, klv.z, klv.w};

    const uint4* qf = g_QF + bh*128*32 + lane;
    const uint4* vf = g_VF + (bh*64*32 + lane)*2;

    float oA0[4] = {}, oA1[4] = {}, oB0[4] = {}, oB1[4] = {};
    float dgA = 0.0f, d8A = 0.0f, dgB = 0.0f, d8B = 0.0f;

    // prologue: prefetch chunk pair (0,1)
    uint4 qA0 = qf[0],  qA1 = qf[32], qB0 = qf[64], qB1 = qf[96];
    uint4 vAa = vf[0],  vAb = vf[1],  vBa = vf[64], vBb = vf[65];
    qf += 128; vf += 128;

    for (int c = 0; c < 64; c += 2) {
        float sAa[4] = {0.f,0.f,0.f,0.f}, sAb[4] = {0.f,0.f,0.f,0.f};
        float sBa[4] = {0.f,0.f,0.f,0.f}, sBb[4] = {0.f,0.f,0.f,0.f};
        mma_bf16(sAa, kh, qA0.x, qA0.y);  mma_bf16(sBa, kh, qB0.x, qB0.y);
        mma_bf16(sAa, kl, qA0.x, qA0.y);  mma_bf16(sBa, kl, qB0.x, qB0.y);
        mma_bf16(sAa, kh, qA0.z, qA0.w);  mma_bf16(sBa, kh, qB0.z, qB0.w);
        mma_bf16(sAb, kh, qA1.x, qA1.y);  mma_bf16(sBb, kh, qB1.x, qB1.y);
        mma_bf16(sAb, kl, qA1.x, qA1.y);  mma_bf16(sBb, kl, qB1.x, qB1.y);
        mma_bf16(sAb, kh, qA1.z, qA1.w);  mma_bf16(sBb, kh, qB1.z, qB1.w);

        if (c < 62) {
            qA0 = qf[0]; qA1 = qf[32]; qB0 = qf[64]; qB1 = qf[96];
            qf += 128;
        }

        // biased exp: P' = 2^(S-12); bias cancels in numerator/denominator ratio
        float pAa0 = ex2(sAa[0]-BIAS), pAa1 = ex2(sAa[1]-BIAS), pAa2 = ex2(sAa[2]-BIAS), pAa3 = ex2(sAa[3]-BIAS);
        float pBa0 = ex2(sBa[0]-BIAS), pBa1 = ex2(sBa[1]-BIAS), pBa2 = ex2(sBa[2]-BIAS), pBa3 = ex2(sBa[3]-BIAS);
        float pAb0 = ex2(sAb[0]-BIAS), pAb1 = ex2(sAb[1]-BIAS), pAb2 = ex2(sAb[2]-BIAS), pAb3 = ex2(sAb[3]-BIAS);
        float pBb0 = ex2(sBb[0]-BIAS), pBb1 = ex2(sBb[1]-BIAS), pBb2 = ex2(sBb[2]-BIAS), pBb3 = ex2(sBb[3]-BIAS);
        dgA += (pAa0 + pAa1) + (pAb0 + pAb1);
        d8A += (pAa2 + pAa3) + (pAb2 + pAb3);
        dgB += (pBa0 + pBa1) + (pBb0 + pBb1);
        d8B += (pBa2 + pBa3) + (pBb2 + pBb3);

        // P -> fp16 A-fragments (satfinite; no residual split needed)
        u32 phA[4], phB[4];
        phA[0] = cvt2h(pAa1, pAa0);  phB[0] = cvt2h(pBa1, pBa0);
        phA[1] = cvt2h(pAa3, pAa2);  phB[1] = cvt2h(pBa3, pBa2);
        phA[2] = cvt2h(pAb1, pAb0);  phB[2] = cvt2h(pBb1, pBb0);
        phA[3] = cvt2h(pAb3, pAb2);  phB[3] = cvt2h(pBb3, pBb2);

        // PV in fp16: o += ph*Vh + ph*Vl
        mma_f16(oA0, phA, vAa.x, vAa.y);  mma_f16(oB0, phB, vBa.x, vBa.y);
        mma_f16(oA0, phA, vAb.x, vAb.y);  mma_f16(oB0, phB, vBb.x, vBb.y);
        mma_f16(oA1, phA, vAa.z, vAa.w);  mma_f16(oB1, phB, vBa.z, vBa.w);
        mma_f16(oA1, phA, vAb.z, vAb.w);  mma_f16(oB1, phB, vBb.z, vBb.w);

        if (c < 62) {
            vAa = vf[0]; vAb = vf[1]; vBa = vf[64]; vBb = vf[65];
            vf += 128;
        }
    }

    float o0[4], o1[4];
    #pragma unroll
    for (int i = 0; i < 4; i++) { o0[i] = oA0[i] + oB0[i]; o1[i] = oA1[i] + oB1[i]; }
    float dg = dgA + dgB, d8 = d8A + d8B;

    dg += __shfl_xor_sync(0xFFFFFFFFu, dg, 1);
    dg += __shfl_xor_sync(0xFFFFFFFFu, dg, 2);
    d8 += __shfl_xor_sync(0xFFFFFFFFu, d8, 1);
    d8 += __shfl_xor_sync(0xFFFFFFFFu, d8, 2);
    float rg = 1.0f / dg, r8 = 1.0f / d8;

    int b = bh >> 3, h = bh & 7;
    int nb0 = jt*8 + w*2;
    uint4 o;
    split2(o0[0]*rg, o0[1]*rg, o.x, o.z);
    split2(o1[0]*rg, o1[1]*rg, o.y, o.w);
    g_HF[((b*8 + h)*128 + nb0)*32 + lane] = o;
    split2(o0[2]*r8, o0[3]*r8, o.x, o.z);
    split2(o1[2]*r8, o1[3]*r8, o.y, o.w);
    g_HF[((b*8 + h)*128 + nb0 + 1)*32 + lane] = o;
}

// ---------------------------------------------------------------------------
// Kernel 4: outproj_mma — output projection on tensor cores (R12 best).
// grid (8 b, 32 l-tiles of 32), 256 thr. Warp: M=64 (4 m-blocks) x N=8.
// ---------------------------------------------------------------------------
__global__ __launch_bounds__(256) void outproj_mma(float* __restrict__ out)
{
    int b = blockIdx.x, lt = blockIdx.y;
    int tid = threadIdx.x, w = tid >> 5, lane = tid & 31;
    int g = lane >> 2, t = lane & 3;
    int mh = w >> 2;
    int nb = lt*4 + (w & 3);

    float acc[4][4] = {};
    #pragma unroll
    for (int kc = 0; kc < 8; kc++) {
        uint4 B = g_HF[((b*8 + kc)*128 + nb)*32 + lane];
        #pragma unroll
        for (int mi = 0; mi < 4; mi++) {
            const uint4* af = g_WoF + (((b*8 + mh*4 + mi)*8 + kc)*32 + lane)*2;
            uint4 Ah = af[0], Al = af[1];
            mma4(acc[mi], Ah, B.x, B.y);
            mma4(acc[mi], Al, B.x, B.y);
            mma4(acc[mi], Ah, B.z, B.w);
        }
    }
    #pragma unroll
    for (int mi = 0; mi < 4; mi++) {
        int m0 = (mh*4 + mi)*16 + g;
        int col = nb*8 + 2*t;
        *(float2*)(out + (b*128 + m0    )*1024 + col) = make_float2(acc[mi][0], acc[mi][1]);
        *(float2*)(out + (b*128 + m0 + 8)*1024 + col) = make_float2(acc[mi][2], acc[mi][3]);
    }
}

// ---------------------------------------------------------------------------
extern "C" void kernel_launch(void* const* d_in, const int* in_sizes, int n_in,
                              void* d_out, int out_size)
{
    const float* x  = (const float*)d_in[0];
    const float* Wq = (const float*)d_in[1];
    const float* Wk = (const float*)d_in[2];
    const float* Wv = (const float*)d_in[3];
    const float* Wo = (const float*)d_in[4];
    float* out = (float*)d_out;

    prep_in<<<512, 256>>>(x, Wq, Wk, Wv, Wo);
    qkv_mma<<<dim3(64, 8), 256>>>();
    attn_kernel<<<dim3(64, 16), 128>>>();
    outproj_mma<<<dim3(8, 32), 256>>>(out);
}

// round 17
// speedup vs baseline: 1.1787x; 1.1787x over previous
#include <cuda_runtime.h>
#include <cstdint>

typedef unsigned long long u64;
typedef unsigned int u32;
typedef unsigned short u16;

#define BH 64

// Fragment images (m16n8k16 per-lane order)
__device__ uint4 g_XF[8*8*128*32];       // x  B-frags bf16 split {b0h,b1h,b0l,b1l}
__device__ uint4 g_WF[64*3*8*32*2];      // Wqkv A-frags bf16 {hi,lo}
__device__ uint4 g_WoF[8*8*8*32*2];      // Wo A-frags bf16 {hi,lo}
__device__ uint4 g_HF[8*8*128*32];       // H  B-frags bf16 (written by attn)
__device__ uint4 g_KF[BH*64*32*2];       // attn A-frags (K FP16, *SCL) {hi,lo}
__device__ uint2 g_QF[BH*128*32];        // attn B-frags (Q FP16 hi only) {b0,b1}
__device__ uint4 g_VF[BH*64*32*2];       // attn B-frags (V FP16) {hi,lo}

// ---------------- helpers ----------------
__device__ __forceinline__ float ex2(float x) {
    float y; asm("ex2.approx.ftz.f32 %0, %1;" : "=f"(y) : "f"(x)); return y;
}
__device__ __forceinline__ u32 cvt2bf(float hi, float lo){
    u32 r; asm("cvt.rn.bf16x2.f32 %0, %1, %2;" : "=r"(r) : "f"(hi), "f"(lo)); return r;
}
// saturating fp16 pack: overflow clamps to max finite (no Inf/NaN possible)
__device__ __forceinline__ u32 cvt2h(float hi, float lo){
    u32 r; asm("cvt.rn.satfinite.f16x2.f32 %0, %1, %2;" : "=r"(r) : "f"(hi), "f"(lo)); return r;
}
__device__ __forceinline__ float f16lo(u32 h){
    float f; asm("{ .reg .b16 l, u; mov.b32 {l, u}, %1; cvt.f32.f16 %0, l; }" : "=f"(f) : "r"(h)); return f;
}
__device__ __forceinline__ float f16hi(u32 h){
    float f; asm("{ .reg .b16 l, u; mov.b32 {l, u}, %1; cvt.f32.f16 %0, u; }" : "=f"(f) : "r"(h)); return f;
}
// bf16 split: (first, second) -> hi bf16x2 (second upper), lo bf16x2 residuals
__device__ __forceinline__ void split2(float a, float b, u32 &hi, u32 &lo) {
    hi = cvt2bf(b, a);
    float la = a - __uint_as_float(hi << 16);
    float lb = b - __uint_as_float(hi & 0xFFFF0000u);
    lo = cvt2bf(lb, la);
}
// fp16 split: (first, second) -> hi f16x2 (second upper), lo f16x2 residuals
__device__ __forceinline__ void split2h(float a, float b, u32 &hi, u32 &lo) {
    hi = cvt2h(b, a);
    lo = cvt2h(b - f16hi(hi), a - f16lo(hi));
}
__device__ __forceinline__ void mma_f16(float d[4], const u32 a[4], u32 b0, u32 b1) {
    asm volatile("mma.sync.aligned.m16n8k16.row.col.f32.f16.f16.f32 "
        "{%0,%1,%2,%3}, {%4,%5,%6,%7}, {%8,%9}, {%0,%1,%2,%3};"
        : "+f"(d[0]),"+f"(d[1]),"+f"(d[2]),"+f"(d[3])
        : "r"(a[0]),"r"(a[1]),"r"(a[2]),"r"(a[3]), "r"(b0),"r"(b1));
}
__device__ __forceinline__ void mma4(float d[4], const uint4 &a, u32 b0, u32 b1) {
    asm volatile("mma.sync.aligned.m16n8k16.row.col.f32.bf16.bf16.f32 "
        "{%0,%1,%2,%3}, {%4,%5,%6,%7}, {%8,%9}, {%0,%1,%2,%3};"
        : "+f"(d[0]),"+f"(d[1]),"+f"(d[2]),"+f"(d[3])
        : "r"(a.x),"r"(a.y),"r"(a.z),"r"(a.w), "r"(b0),"r"(b1));
}

// ---------------------------------------------------------------------------
// Kernel 1: prep_in — fragment images for x, Wqkv, Wo. grid 512 x 256.
// ---------------------------------------------------------------------------
__global__ __launch_bounds__(256) void prep_in(
    const float* __restrict__ x,
    const float* __restrict__ Wq, const float* __restrict__ Wk,
    const float* __restrict__ Wv, const float* __restrict__ Wo)
{
    int tid = blockIdx.x*256 + threadIdx.x;
    int stride = gridDim.x*256;

    // x B-fragments: 262144 entries
    for (int e = tid; e < 8*8*128*32; e += stride) {
        int lane = e & 31, nb = (e >> 5) & 127, kc = (e >> 12) & 7, b = e >> 15;
        int g = lane >> 2, t = lane & 3;
        const float* xb = x + b*128*1024 + nb*8 + g;
        int d = kc*16 + 2*t;
        float f0 = xb[(d    )*1024], f1 = xb[(d + 1)*1024];
        float f2 = xb[(d + 8)*1024], f3 = xb[(d + 9)*1024];
        uint4 o; u32 l0, l1;
        split2(f0, f1, o.x, l0);
        split2(f2, f3, o.y, l1);
        o.z = l0; o.w = l1;
        g_XF[e] = o;
    }
    // Wqkv A-fragments: 49152 entries
    for (int e = tid; e < 64*3*8*32; e += stride) {
        int lane = e & 31, kc = (e >> 5) & 7;
        int mb = (e >> 8) % 3, bh = (e >> 8) / 3;
        int g = lane >> 2, t = lane & 3;
        int b = bh >> 3, h = bh & 7;
        int m0 = mb*16 + g, m1 = m0 + 8, k0 = kc*16 + 2*t, k2 = k0 + 8;
        const float* Wm0 = (m0 < 16) ? Wq : ((m0 < 32) ? Wk : Wv);
        const float* Wm1 = (m1 < 16) ? Wq : ((m1 < 32) ? Wk : Wv);
        const float* r0p = Wm0 + ((h*8 + b)*16 + (m0 & 15))*128;
        const float* r1p = Wm1 + ((h*8 + b)*16 + (m1 & 15))*128;
        uint4 hi, lo;
        split2(r0p[k0], r0p[k0+1], hi.x, lo.x);
        split2(r1p[k0], r1p[k0+1], hi.y, lo.y);
        split2(r0p[k2], r0p[k2+1], hi.z, lo.z);
        split2(r1p[k2], r1p[k2+1], hi.w, lo.w);
        g_WF[e*2] = hi; g_WF[e*2 + 1] = lo;
    }
    // Wo A-fragments: 16384 entries
    for (int e = tid; e < 8*8*8*32; e += stride) {
        int lane = e & 31, kc = (e >> 5) & 7, mb = (e >> 8) & 7, b = e >> 11;
        int g = lane >> 2, t = lane & 3;
        int m0 = mb*16 + g, m1 = m0 + 8, k0 = kc*16 + 2*t, k2 = k0 + 8;
        const float* W = Wo + b*128*128;
        uint4 hi, lo;
        split2(W[m0*128 + k0], W[m0*128 + k0+1], hi.x, lo.x);
        split2(W[m1*128 + k0], W[m1*128 + k0+1], hi.y, lo.y);
        split2(W[m0*128 + k2], W[m0*128 + k2+1], hi.z, lo.z);
        split2(W[m1*128 + k2], W[m1*128 + k2+1], hi.w, lo.w);
        g_WoF[e*2] = hi; g_WoF[e*2 + 1] = lo;
    }
}

// ---------------------------------------------------------------------------
// Kernel 2: qkv_mma — QKV projection on tensor cores, fused with attn
// fragment construction. K/Q/V attn fragments all FP16.
// grid (64 bh, 8 l-tiles of 128), 256 thr.
// ---------------------------------------------------------------------------
__global__ __launch_bounds__(256) void qkv_mma()
{
    __shared__ float sQKV[48][128];

    int bh = blockIdx.x, b = bh >> 3;
    int lt = blockIdx.y;
    int tid = threadIdx.x, w = tid >> 5, lane = tid & 31;
    int g = lane >> 2, t = lane & 3;
    int nb0 = lt*16 + w*2;

    float acc[3][2][4] = {};
    #pragma unroll
    for (int kc = 0; kc < 8; kc++) {
        uint4 B0 = g_XF[((b*8 + kc)*128 + nb0    )*32 + lane];
        uint4 B1 = g_XF[((b*8 + kc)*128 + nb0 + 1)*32 + lane];
        #pragma unroll
        for (int mb = 0; mb < 3; mb++) {
            const uint4* af = g_WF + (((bh*3 + mb)*8 + kc)*32 + lane)*2;
            uint4 Ah = af[0], Al = af[1];
            mma4(acc[mb][0], Ah, B0.x, B0.y);
            mma4(acc[mb][0], Al, B0.x, B0.y);
            mma4(acc[mb][0], Ah, B0.z, B0.w);
            mma4(acc[mb][1], Ah, B1.x, B1.y);
            mma4(acc[mb][1], Al, B1.x, B1.y);
            mma4(acc[mb][1], Ah, B1.z, B1.w);
        }
    }
    // stage to smem (local cols)
    #pragma unroll
    for (int mb = 0; mb < 3; mb++) {
        #pragma unroll
        for (int nbi = 0; nbi < 2; nbi++) {
            int col = (w*2 + nbi)*8 + 2*t;
            int r0 = mb*16 + g;
            sQKV[r0    ][col    ] = acc[mb][nbi][0];
            sQKV[r0    ][col + 1] = acc[mb][nbi][1];
            sQKV[r0 + 8][col    ] = acc[mb][nbi][2];
            sQKV[r0 + 8][col + 1] = acc[mb][nbi][3];
        }
    }
    __syncthreads();

    // Phase 2: fragment construction (sourced from smem)
    const float SCLF = 0.25f * 1.4426950408889634f;  // scale * log2(e)
    {   // K A-fragments (scaled, FP16 split)
        int bb = tid >> 5, l2 = tid & 31, g2 = l2 >> 2, t2 = l2 & 3;
        int c0 = bb*16 + g2, c1 = c0 + 8;
        int k0 = 2*t2, k2 = 2*t2 + 8;
        float f0 = sQKV[16 + k0    ][c0] * SCLF;
        float f1 = sQKV[16 + k0 + 1][c0] * SCLF;
        float f2 = sQKV[16 + k0    ][c1] * SCLF;
        float f3 = sQKV[16 + k0 + 1][c1] * SCLF;
        float f4 = sQKV[16 + k2    ][c0] * SCLF;
        float f5 = sQKV[16 + k2 + 1][c0] * SCLF;
        float f6 = sQKV[16 + k2    ][c1] * SCLF;
        float f7 = sQKV[16 + k2 + 1][c1] * SCLF;
        uint4 hi, lo;
        split2h(f0, f1, hi.x, lo.x);
        split2h(f2, f3, hi.y, lo.y);
        split2h(f4, f5, hi.z, lo.z);
        split2h(f6, f7, hi.w, lo.w);
        int idx = ((bh*64 + lt*8 + bb)*32 + l2)*2;
        g_KF[idx] = hi; g_KF[idx + 1] = lo;
    }
    #pragma unroll
    for (int s2 = 0; s2 < 2; s2++) {  // Q B-fragments (FP16 hi only)
        int e = s2*256 + tid;
        int cc = e >> 5, l2 = e & 31, g2 = l2 >> 2, t2 = l2 & 3;
        int i = cc*8 + g2;
        float f0 = sQKV[2*t2    ][i];
        float f1 = sQKV[2*t2 + 1][i];
        float f2 = sQKV[2*t2 + 8][i];
        float f3 = sQKV[2*t2 + 9][i];
        uint2 o2;
        o2.x = cvt2h(f1, f0);
        o2.y = cvt2h(f3, f2);
        g_QF[(bh*128 + lt*16 + cc)*32 + l2] = o2;
    }
    {   // V B-fragments (FP16 split hi/lo)
        int bb = tid >> 5, l2 = tid & 31, g2 = l2 >> 2, t2 = l2 & 3;
        int i0 = bb*16;
        float a0 = sQKV[32 + g2    ][i0 + 2*t2];
        float a1 = sQKV[32 + g2    ][i0 + 2*t2 + 1];
        float a2 = sQKV[32 + g2    ][i0 + 2*t2 + 8];
        float a3 = sQKV[32 + g2    ][i0 + 2*t2 + 9];
        float c0 = sQKV[32 + g2 + 8][i0 + 2*t2];
        float c1 = sQKV[32 + g2 + 8][i0 + 2*t2 + 1];
        float c2 = sQKV[32 + g2 + 8][i0 + 2*t2 + 8];
        float c3 = sQKV[32 + g2 + 8][i0 + 2*t2 + 9];
        uint4 hi, lo;
        split2h(a0, a1, hi.x, lo.x);
        split2h(a2, a3, hi.y, lo.y);
        split2h(c0, c1, hi.z, lo.z);
        split2h(c2, c3, hi.w, lo.w);
        int idx = ((bh*64 + lt*8 + bb)*32 + l2)*2;
        g_VF[idx] = hi; g_VF[idx + 1] = lo;
    }
}

// ---------------------------------------------------------------------------
// Kernel 3: attn — minimal-instruction fp16 flash attention, single wave.
// grid (64 bh, 16 jtiles of 64), 128 thr, 8 CTAs/SM (<=64 regs).
// Scores: S = Kh Qh + Kl Qh (fp16 2-term). P = 2^(S-12) fp16 satfinite.
// PV: o += ph Vh + ph Vl. 8 mmas + 8 ex2 per 16-i chunk.
// ---------------------------------------------------------------------------
#define BIAS 12.0f
__global__ __launch_bounds__(128, 8) void attn_kernel()
{
    int bh = blockIdx.x, jt = blockIdx.y, tid = threadIdx.x;
    int w = tid >> 5, lane = tid & 31;

    const uint4* kf = g_KF + ((bh*64 + jt*4 + w)*32 + lane)*2;
    uint4 khv = kf[0], klv = kf[1];
    u32 kh[4] = {khv.x, khv.y, khv.z, khv.w};
    u32 kl[4] = {klv.x, klv.y, klv.z, klv.w};

    const uint2* qf = g_QF + bh*128*32 + lane;
    const uint4* vf = g_VF + (bh*64*32 + lane)*2;

    float o0[4] = {}, o1[4] = {};
    float dg = 0.0f, d8 = 0.0f;

    // prologue: prefetch chunk 0
    uint2 q0 = qf[0], q1 = qf[32];
    uint4 va = vf[0], vb = vf[1];
    qf += 64; vf += 64;

    #pragma unroll 2
    for (int c = 0; c < 64; c++) {
        uint2 nq0, nq1; uint4 nva, nvb;
        if (c < 63) {
            nq0 = qf[0]; nq1 = qf[32];
            nva = vf[0]; nvb = vf[1];
            qf += 64; vf += 64;
        }

        float sa[4] = {0.f,0.f,0.f,0.f}, sb[4] = {0.f,0.f,0.f,0.f};
        mma_f16(sa, kh, q0.x, q0.y);
        mma_f16(sa, kl, q0.x, q0.y);
        mma_f16(sb, kh, q1.x, q1.y);
        mma_f16(sb, kl, q1.x, q1.y);

        float pa0 = ex2(sa[0]-BIAS), pa1 = ex2(sa[1]-BIAS), pa2 = ex2(sa[2]-BIAS), pa3 = ex2(sa[3]-BIAS);
        float pb0 = ex2(sb[0]-BIAS), pb1 = ex2(sb[1]-BIAS), pb2 = ex2(sb[2]-BIAS), pb3 = ex2(sb[3]-BIAS);
        dg += (pa0 + pa1) + (pb0 + pb1);
        d8 += (pa2 + pa3) + (pb2 + pb3);

        u32 ph[4];
        ph[0] = cvt2h(pa1, pa0);
        ph[1] = cvt2h(pa3, pa2);
        ph[2] = cvt2h(pb1, pb0);
        ph[3] = cvt2h(pb3, pb2);

        mma_f16(o0, ph, va.x, va.y);
        mma_f16(o0, ph, vb.x, vb.y);
        mma_f16(o1, ph, va.z, va.w);
        mma_f16(o1, ph, vb.z, vb.w);

        q0 = nq0; q1 = nq1; va = nva; vb = nvb;
    }

    dg += __shfl_xor_sync(0xFFFFFFFFu, dg, 1);
    dg += __shfl_xor_sync(0xFFFFFFFFu, dg, 2);
    d8 += __shfl_xor_sync(0xFFFFFFFFu, d8, 1);
    d8 += __shfl_xor_sync(0xFFFFFFFFu, d8, 2);
    float rg = 1.0f / dg, r8 = 1.0f / d8;

    int b = bh >> 3, h = bh & 7;
    int nb0 = jt*8 + w*2;
    uint4 o;
    split2(o0[0]*rg, o0[1]*rg, o.x, o.z);   // b0 of nb0 (v=2t,2t+1 @ col j0)
    split2(o1[0]*rg, o1[1]*rg, o.y, o.w);   // b1 of nb0 (v=2t+8,2t+9)
    g_HF[((b*8 + h)*128 + nb0)*32 + lane] = o;
    split2(o0[2]*r8, o0[3]*r8, o.x, o.z);   // b0 of nb1 (col j0+8)
    split2(o1[2]*r8, o1[3]*r8, o.y, o.w);
    g_HF[((b*8 + h)*128 + nb0 + 1)*32 + lane] = o;
}

// ---------------------------------------------------------------------------
// Kernel 4: outproj_mma — output projection on tensor cores (R12 best).
// grid (8 b, 32 l-tiles of 32), 256 thr. Warp: M=64 (4 m-blocks) x N=8.
// ---------------------------------------------------------------------------
__global__ __launch_bounds__(256) void outproj_mma(float* __restrict__ out)
{
    int b = blockIdx.x, lt = blockIdx.y;
    int tid = threadIdx.x, w = tid >> 5, lane = tid & 31;
    int g = lane >> 2, t = lane & 3;
    int mh = w >> 2;
    int nb = lt*4 + (w & 3);

    float acc[4][4] = {};
    #pragma unroll
    for (int kc = 0; kc < 8; kc++) {
        uint4 B = g_HF[((b*8 + kc)*128 + nb)*32 + lane];
        #pragma unroll
        for (int mi = 0; mi < 4; mi++) {
            const uint4* af = g_WoF + (((b*8 + mh*4 + mi)*8 + kc)*32 + lane)*2;
            uint4 Ah = af[0], Al = af[1];
            mma4(acc[mi], Ah, B.x, B.y);
            mma4(acc[mi], Al, B.x, B.y);
            mma4(acc[mi], Ah, B.z, B.w);
        }
    }
    #pragma unroll
    for (int mi = 0; mi < 4; mi++) {
        int m0 = (mh*4 + mi)*16 + g;
        int col = nb*8 + 2*t;
        *(float2*)(out + (b*128 + m0    )*1024 + col) = make_float2(acc[mi][0], acc[mi][1]);
        *(float2*)(out + (b*128 + m0 + 8)*1024 + col) = make_float2(acc[mi][2], acc[mi][3]);
    }
}

// ---------------------------------------------------------------------------
extern "C" void kernel_launch(void* const* d_in, const int* in_sizes, int n_in,
                              void* d_out, int out_size)
{
    const float* x  = (const float*)d_in[0];
    const float* Wq = (const float*)d_in[1];
    const float* Wk = (const float*)d_in[2];
    const float* Wv = (const float*)d_in[3];
    const float* Wo = (const float*)d_in[4];
    float* out = (float*)d_out;

    prep_in<<<512, 256>>>(x, Wq, Wk, Wv, Wo);
    qkv_mma<<<dim3(64, 8), 256>>>();
    attn_kernel<<<dim3(64, 16), 128>>>();
    outproj_mma<<<dim3(8, 32), 256>>>(out);
}